// round 1
// baseline (speedup 1.0000x reference)
#include <cuda_runtime.h>

#define Nn   100000
#define Ee   1600000
#define HIDD 128
#define HEADS 4
#define CH   32
#define LL   2
#define GG   64

// ---------------- scratch (static device globals; no allocation) -----------
__device__ __align__(16) float    g_h[Nn*HIDD];
__device__ __align__(16) float    g_xs[Nn*HIDD];
__device__ __align__(16) float    g_out[Nn*HIDD];
__device__ __align__(16) float    g_as[Nn*HEADS];
__device__ __align__(16) float    g_ad[Nn*HEADS];
__device__ __align__(16) unsigned g_amax[Nn*HEADS];
__device__ __align__(16) float    g_denom[Nn*HEADS];
__device__ __align__(16) float    g_p[Ee*HEADS];
__device__ __align__(16) float    g_uv[2*LL*HEADS];
__device__ __align__(16) float    g_pooled[GG*HIDD];
__device__           float        g_cnt[GG];
__device__ __align__(16) float    g_z[GG*64];

// monotone float->uint encoding for atomicMax over signed floats
__device__ __forceinline__ unsigned f2u_ord(float f) {
    unsigned u = __float_as_uint(f);
    return (u & 0x80000000u) ? ~u : (u | 0x80000000u);
}
__device__ __forceinline__ float u2f_ord(unsigned e) {
    return (e & 0x80000000u) ? __uint_as_float(e ^ 0x80000000u)
                             : __uint_as_float(~e);
}

// ---------------- node encoder: h = x * enc_w + enc_b ----------------------
__global__ void k_enc(const float* __restrict__ x, const float* __restrict__ ew,
                      const float* __restrict__ eb) {
    int i = blockIdx.x * blockDim.x + threadIdx.x;
    if (i >= Nn * HIDD) return;
    int n = i >> 7, c = i & 127;
    g_h[i] = x[n] * ew[c] + eb[c];
}

// ---------------- precompute a_e coefficients u,v (rank-1 edge path) -------
// a_e[e,h] = edge_attr[e]*u[l,h] + v[l,h]
__global__ void k_uv(const float* __restrict__ eenc_w, const float* __restrict__ eenc_b,
                     const float* __restrict__ lew, const float* __restrict__ att_e) {
    int tid = threadIdx.x;                 // 256 = L*H*C
    int l = tid >> 7, h = (tid >> 5) & 3, c = tid & 31;
    const float* W = lew + l * HIDD * HIDD;
    int col = h * CH + c;
    float wc = 0.f, bc = 0.f;
    for (int k = 0; k < HIDD; k++) {
        float w = W[k * HIDD + col];
        wc += eenc_w[k] * w;
        bc += eenc_b[k] * w;
    }
    float ae = att_e[l * HEADS * CH + h * CH + c];
    float uu = wc * ae, vv = bc * ae;
    for (int off = 16; off; off >>= 1) {
        uu += __shfl_down_sync(0xffffffffu, uu, off);
        vv += __shfl_down_sync(0xffffffffu, vv, off);
    }
    if (c == 0) {
        g_uv[l * HEADS + h] = uu;
        g_uv[LL * HEADS + l * HEADS + h] = vv;
    }
}

// ---------------- per-layer accumulator init -------------------------------
__global__ void k_init() {
    int i = blockIdx.x * blockDim.x + threadIdx.x;
    if (i < Nn * HIDD) g_out[i] = 0.f;
    if (i < Nn * HEADS) { g_amax[i] = 0u; g_denom[i] = 0.f; }
}

// ---------------- xs = h @ W (tile 64x128, K staged in 32-chunks) ----------
__global__ void k_gemm(const float* __restrict__ W) {
    __shared__ float Ws[32][128];
    __shared__ float As[64][32];
    int tid = threadIdx.x;         // 256
    int tx = tid & 31, ty = tid >> 5;
    int br = blockIdx.x * 64;
    float acc[8][4];
#pragma unroll
    for (int r = 0; r < 8; r++) { acc[r][0]=acc[r][1]=acc[r][2]=acc[r][3]=0.f; }

    for (int kt = 0; kt < 4; kt++) {
        // stage W tile [32][128]
#pragma unroll
        for (int q = 0; q < 4; q++) {
            int f = tid + q * 256;           // float4 id, 0..1023
            int row = f >> 5, col = (f & 31) * 4;
            float4 w4 = *(const float4*)&W[(kt * 32 + row) * HIDD + col];
            *(float4*)&Ws[row][col] = w4;
        }
        // stage A tile [64][32]
#pragma unroll
        for (int q = 0; q < 2; q++) {
            int f = tid + q * 256;           // 0..511
            int row = f >> 3, col = (f & 7) * 4;
            int gr = br + row;
            float4 a4 = make_float4(0.f, 0.f, 0.f, 0.f);
            if (gr < Nn) a4 = *(const float4*)&g_h[gr * HIDD + kt * 32 + col];
            *(float4*)&As[row][col] = a4;
        }
        __syncthreads();
#pragma unroll
        for (int k = 0; k < 32; k++) {
            float4 b = *(float4*)&Ws[k][tx * 4];
#pragma unroll
            for (int r = 0; r < 8; r++) {
                float a = As[ty * 8 + r][k];
                acc[r][0] += a * b.x;
                acc[r][1] += a * b.y;
                acc[r][2] += a * b.z;
                acc[r][3] += a * b.w;
            }
        }
        __syncthreads();
    }
#pragma unroll
    for (int r = 0; r < 8; r++) {
        int gr = br + ty * 8 + r;
        if (gr < Nn) {
            float4 o = make_float4(acc[r][0], acc[r][1], acc[r][2], acc[r][3]);
            *(float4*)&g_xs[gr * HIDD + tx * 4] = o;
        }
    }
}

// ---------------- attention logits a_s, a_d (warp per node) ----------------
__global__ void k_att(const float* __restrict__ att_src, const float* __restrict__ att_dst,
                      int l) {
    int gt = blockIdx.x * blockDim.x + threadIdx.x;
    int n = gt >> 5, lane = threadIdx.x & 31;
    if (n >= Nn) return;
    float4 v = *(const float4*)&g_xs[n * HIDD + lane * 4];
    int h = lane >> 3;
    int off = l * HEADS * CH + h * CH + (lane & 7) * 4;
    float4 s = *(const float4*)&att_src[off];
    float4 d = *(const float4*)&att_dst[off];
    float ps = v.x * s.x + v.y * s.y + v.z * s.z + v.w * s.w;
    float pd = v.x * d.x + v.y * d.y + v.z * d.z + v.w * d.w;
    for (int o = 4; o; o >>= 1) {
        ps += __shfl_down_sync(0xffffffffu, ps, o, 8);
        pd += __shfl_down_sync(0xffffffffu, pd, o, 8);
    }
    if ((lane & 7) == 0) {
        g_as[n * HEADS + h] = ps;
        g_ad[n * HEADS + h] = pd;
    }
}

// ---------------- alpha = leaky_relu(a_s[src]+a_d[dst]+a_e) + segmax -------
__global__ void k_alpha(const int* __restrict__ ei, const float* __restrict__ ea, int l) {
    int e = blockIdx.x * blockDim.x + threadIdx.x;
    if (e >= Ee) return;
    int s = ei[e], d = ei[Ee + e];
    float4 as4 = *(const float4*)&g_as[s * 4];
    float4 ad4 = *(const float4*)&g_ad[d * 4];
    float a = ea[e];
    float4 u4 = *(const float4*)&g_uv[l * 4];
    float4 v4 = *(const float4*)&g_uv[LL * HEADS + l * 4];
    float al[4];
    al[0] = as4.x + ad4.x + a * u4.x + v4.x;
    al[1] = as4.y + ad4.y + a * u4.y + v4.y;
    al[2] = as4.z + ad4.z + a * u4.z + v4.z;
    al[3] = as4.w + ad4.w + a * u4.w + v4.w;
#pragma unroll
    for (int h = 0; h < 4; h++) {
        al[h] = (al[h] > 0.f) ? al[h] : 0.2f * al[h];
        atomicMax(&g_amax[d * 4 + h], f2u_ord(al[h]));
    }
    *(float4*)&g_p[e * 4] = make_float4(al[0], al[1], al[2], al[3]);
}

// ---------------- decode amax; empty segments -> 0 -------------------------
__global__ void k_amaxfix() {
    int i = blockIdx.x * blockDim.x + threadIdx.x;
    if (i >= Nn * HEADS) return;
    unsigned u = g_amax[i];
    float f = (u == 0u) ? 0.f : u2f_ord(u);
    g_amax[i] = __float_as_uint(f);
}

// ---------------- p = exp(alpha - amax[dst]); denom += p -------------------
__global__ void k_pexp(const int* __restrict__ ei) {
    int e = blockIdx.x * blockDim.x + threadIdx.x;
    if (e >= Ee) return;
    int d = ei[Ee + e];
    float4 al = *(const float4*)&g_p[e * 4];
    uint4 am = *(const uint4*)&g_amax[d * 4];
    float p0 = __expf(al.x - __uint_as_float(am.x));
    float p1 = __expf(al.y - __uint_as_float(am.y));
    float p2 = __expf(al.z - __uint_as_float(am.z));
    float p3 = __expf(al.w - __uint_as_float(am.w));
    atomicAdd(&g_denom[d * 4 + 0], p0);
    atomicAdd(&g_denom[d * 4 + 1], p1);
    atomicAdd(&g_denom[d * 4 + 2], p2);
    atomicAdd(&g_denom[d * 4 + 3], p3);
    *(float4*)&g_p[e * 4] = make_float4(p0, p1, p2, p3);
}

// ---------------- message scatter: out[dst] += xs[src]*attn (warp/edge) ----
__global__ void k_msg(const int* __restrict__ ei) {
    long long idx = (long long)blockIdx.x * blockDim.x + threadIdx.x;
    int e = (int)(idx >> 5);
    int lane = threadIdx.x & 31;
    if (e >= Ee) return;
    int s = ei[e], d = ei[Ee + e];
    int h = lane >> 3;
    float attn = g_p[e * 4 + h] / (g_denom[d * 4 + h] + 1e-16f);
    float4 v = *(const float4*)&g_xs[s * HIDD + lane * 4];
    float* o = &g_out[d * HIDD + lane * 4];
    atomicAdd(o + 0, v.x * attn);
    atomicAdd(o + 1, v.y * attn);
    atomicAdd(o + 2, v.z * attn);
    atomicAdd(o + 3, v.w * attn);
}

// ---------------- BN(eval) + ReLU + residual -> h --------------------------
__global__ void k_bnres(const float* __restrict__ conv_b, const float* __restrict__ gamma,
                        const float* __restrict__ beta, const float* __restrict__ mean,
                        const float* __restrict__ var, int l) {
    int i = blockIdx.x * blockDim.x + threadIdx.x;
    if (i >= Nn * HIDD) return;
    int c = (i & 127) + l * HIDD;
    float o = g_out[i] + conv_b[c];
    o = (o - mean[c]) * rsqrtf(var[c] + 1e-5f) * gamma[c] + beta[c];
    g_h[i] = fmaxf(o, 0.f) + g_h[i];
}

// ---------------- pooling ---------------------------------------------------
__global__ void k_zeropool() {
    int i = blockIdx.x * blockDim.x + threadIdx.x;
    if (i < GG * HIDD) g_pooled[i] = 0.f;
    if (i < GG) g_cnt[i] = 0.f;
}

#define NPB 256
__global__ void k_pool(const int* __restrict__ batch) {
    int c = threadIdx.x;              // 128 channels
    int n0 = blockIdx.x * NPB;
    int n1 = min(n0 + NPB, Nn);
    int cur = -1; float s = 0.f; float cn = 0.f;
    for (int n = n0; n < n1; n++) {
        int g = batch[n];
        if (g != cur) {
            if (cur >= 0) {
                atomicAdd(&g_pooled[cur * HIDD + c], s);
                if (c == 0) atomicAdd(&g_cnt[cur], cn);
            }
            cur = g; s = 0.f; cn = 0.f;
        }
        s += g_h[n * HIDD + c];
        cn += 1.f;
    }
    if (cur >= 0) {
        atomicAdd(&g_pooled[cur * HIDD + c], s);
        if (c == 0) atomicAdd(&g_cnt[cur], cn);
    }
}

// ---------------- classifier head ------------------------------------------
__global__ void k_mlp1(const float* __restrict__ w1, const float* __restrict__ b1) {
    int i = blockIdx.x * blockDim.x + threadIdx.x;   // GG*64
    if (i >= GG * 64) return;
    int g = i >> 6, j = i & 63;
    float cnt = fmaxf(g_cnt[g], 1.f);
    float s = 0.f;
    for (int k = 0; k < HIDD; k++) s += g_pooled[g * HIDD + k] * w1[k * 64 + j];
    g_z[i] = fmaxf(s / cnt + b1[j], 0.f);
}

__global__ void k_mlp2(const float* __restrict__ w2, const float* __restrict__ b2,
                       float* __restrict__ out) {
    int g = threadIdx.x;
    if (g >= GG) return;
    float s = b2[0];
    for (int j = 0; j < 64; j++) s += g_z[g * 64 + j] * w2[j];
    out[g] = 1.f / (1.f + __expf(-s));
}

// ---------------- launch ----------------------------------------------------
extern "C" void kernel_launch(void* const* d_in, const int* in_sizes, int n_in,
                              void* d_out, int out_size) {
    const float* x        = (const float*)d_in[0];
    const float* ea       = (const float*)d_in[1];
    const int*   ei       = (const int*)  d_in[2];
    const int*   batch    = (const int*)  d_in[3];
    const float* enc_w    = (const float*)d_in[4];
    const float* enc_b    = (const float*)d_in[5];
    const float* eenc_w   = (const float*)d_in[6];
    const float* eenc_b   = (const float*)d_in[7];
    const float* lin_w    = (const float*)d_in[8];
    const float* att_src  = (const float*)d_in[9];
    const float* att_dst  = (const float*)d_in[10];
    const float* att_edge = (const float*)d_in[11];
    const float* lin_ew   = (const float*)d_in[12];
    const float* conv_b   = (const float*)d_in[13];
    const float* bn_gamma = (const float*)d_in[14];
    const float* bn_beta  = (const float*)d_in[15];
    const float* bn_mean  = (const float*)d_in[16];
    const float* bn_var   = (const float*)d_in[17];
    const float* w1       = (const float*)d_in[18];
    const float* b1       = (const float*)d_in[19];
    const float* w2       = (const float*)d_in[20];
    const float* b2       = (const float*)d_in[21];
    float* out = (float*)d_out;

    const int TB = 256;
    int gridNH = (Nn * HIDD + TB - 1) / TB;
    int gridE  = (Ee + TB - 1) / TB;
    int gridE32 = (int)(((long long)Ee * 32 + TB - 1) / TB);
    int gridN4 = (Nn * HEADS + TB - 1) / TB;
    int gridNW = (Nn * 32 + TB - 1) / TB;

    k_enc<<<gridNH, TB>>>(x, enc_w, enc_b);
    k_uv<<<1, 256>>>(eenc_w, eenc_b, lin_ew, att_edge);

    for (int l = 0; l < LL; l++) {
        k_init<<<gridNH, TB>>>();
        k_gemm<<<(Nn + 63) / 64, 256>>>(lin_w + l * HIDD * HIDD);
        k_att<<<gridNW, TB>>>(att_src, att_dst, l);
        k_alpha<<<gridE, TB>>>(ei, ea, l);
        k_amaxfix<<<gridN4, TB>>>();
        k_pexp<<<gridE, TB>>>(ei);
        k_msg<<<gridE32, TB>>>(ei);
        k_bnres<<<gridNH, TB>>>(conv_b, bn_gamma, bn_beta, bn_mean, bn_var, l);
    }

    k_zeropool<<<(GG * HIDD + TB - 1) / TB, TB>>>();
    k_pool<<<(Nn + NPB - 1) / NPB, 128>>>(batch);
    k_mlp1<<<(GG * 64 + TB - 1) / TB, TB>>>(w1, b1);
    k_mlp2<<<1, 64>>>(w2, b2, out);
}

// round 2
// speedup vs baseline: 2.5410x; 2.5410x over previous
#include <cuda_runtime.h>

#define Nn   100000
#define Ee   1600000
#define HIDD 128
#define HEADS 4
#define CH   32
#define LL   2
#define GG   64
#define NCHUNK ((Nn + 255) / 256)   // 391

// ---------------- scratch (static device globals; no allocation) -----------
__device__ __align__(16) float    g_h[Nn*HIDD];
__device__ __align__(16) float    g_xs[Nn*HIDD];
__device__ __align__(16) float    g_as[Nn*HEADS];
__device__ __align__(16) float    g_ad[Nn*HEADS];
__device__ __align__(16) float    g_p[Ee*HEADS];      // per-edge alpha scratch
__device__ __align__(16) float    g_uv[2*LL*HEADS];
__device__ __align__(16) float    g_pooled[GG*HIDD];
__device__           float        g_cnt[GG];
__device__ __align__(16) float    g_z[GG*64];
// CSR by destination
__device__ __align__(16) int      g_deg[Nn];
__device__ __align__(16) int      g_row[Nn + 1];
__device__ __align__(16) int      g_cur[Nn];
__device__ __align__(16) int      g_bsum[NCHUNK];
__device__ __align__(16) int      g_boff[NCHUNK];
__device__ __align__(16) int      g_srcs[Ee];
__device__ __align__(16) float    g_eas[Ee];

// ---------------- node encoder: h = x * enc_w + enc_b ; zero degree --------
__global__ void k_enc(const float* __restrict__ x, const float* __restrict__ ew,
                      const float* __restrict__ eb) {
    int i = blockIdx.x * blockDim.x + threadIdx.x;
    if (i < Nn) g_deg[i] = 0;
    if (i >= Nn * HIDD) return;
    int n = i >> 7, c = i & 127;
    g_h[i] = x[n] * ew[c] + eb[c];
}

// ---------------- precompute a_e coefficients u,v (rank-1 edge path) -------
__global__ void k_uv(const float* __restrict__ eenc_w, const float* __restrict__ eenc_b,
                     const float* __restrict__ lew, const float* __restrict__ att_e) {
    int tid = threadIdx.x;                 // 256 = L*H*C
    int l = tid >> 7, h = (tid >> 5) & 3, c = tid & 31;
    const float* W = lew + l * HIDD * HIDD;
    int col = h * CH + c;
    float wc = 0.f, bc = 0.f;
    for (int k = 0; k < HIDD; k++) {
        float w = W[k * HIDD + col];
        wc += eenc_w[k] * w;
        bc += eenc_b[k] * w;
    }
    float ae = att_e[l * HEADS * CH + h * CH + c];
    float uu = wc * ae, vv = bc * ae;
    for (int off = 16; off; off >>= 1) {
        uu += __shfl_down_sync(0xffffffffu, uu, off);
        vv += __shfl_down_sync(0xffffffffu, vv, off);
    }
    if (c == 0) {
        g_uv[l * HEADS + h] = uu;
        g_uv[LL * HEADS + l * HEADS + h] = vv;
    }
}

// ---------------- CSR build -------------------------------------------------
__global__ void k_hist(const int* __restrict__ ei) {
    int e = blockIdx.x * blockDim.x + threadIdx.x;
    if (e >= Ee) return;
    atomicAdd(&g_deg[ei[Ee + e]], 1);
}

__global__ void k_scan1() {
    __shared__ int sd[256];
    int t = threadIdx.x;
    int i = blockIdx.x * 256 + t;
    int v = (i < Nn) ? g_deg[i] : 0;
    sd[t] = v;
    __syncthreads();
    for (int off = 1; off < 256; off <<= 1) {
        int x = (t >= off) ? sd[t - off] : 0;
        __syncthreads();
        sd[t] += x;
        __syncthreads();
    }
    if (i < Nn) g_row[i] = sd[t] - v;          // exclusive within chunk
    if (t == 255) g_bsum[blockIdx.x] = sd[255];
}

__global__ void k_scan2() {
    if (threadIdx.x == 0) {
        int run = 0;
        for (int b = 0; b < NCHUNK; b++) { g_boff[b] = run; run += g_bsum[b]; }
    }
}

__global__ void k_scan3() {
    int i = blockIdx.x * blockDim.x + threadIdx.x;
    if (i == 0) g_row[Nn] = Ee;
    if (i >= Nn) return;
    int r = g_row[i] + g_boff[i >> 8];
    g_row[i] = r;
    g_cur[i] = r;
}

__global__ void k_scatter(const int* __restrict__ ei, const float* __restrict__ ea) {
    int e = blockIdx.x * blockDim.x + threadIdx.x;
    if (e >= Ee) return;
    int d = ei[Ee + e];
    int pos = atomicAdd(&g_cur[d], 1);
    g_srcs[pos] = ei[e];
    g_eas[pos] = ea[e];
}

// ---------------- xs = h @ W (tile 64x128, K staged in 32-chunks) ----------
__global__ void k_gemm(const float* __restrict__ W) {
    __shared__ float Ws[32][128];
    __shared__ float As[64][32];
    int tid = threadIdx.x;         // 256
    int tx = tid & 31, ty = tid >> 5;
    int br = blockIdx.x * 64;
    float acc[8][4];
#pragma unroll
    for (int r = 0; r < 8; r++) { acc[r][0]=acc[r][1]=acc[r][2]=acc[r][3]=0.f; }

    for (int kt = 0; kt < 4; kt++) {
#pragma unroll
        for (int q = 0; q < 4; q++) {
            int f = tid + q * 256;
            int row = f >> 5, col = (f & 31) * 4;
            float4 w4 = *(const float4*)&W[(kt * 32 + row) * HIDD + col];
            *(float4*)&Ws[row][col] = w4;
        }
#pragma unroll
        for (int q = 0; q < 2; q++) {
            int f = tid + q * 256;
            int row = f >> 3, col = (f & 7) * 4;
            int gr = br + row;
            float4 a4 = make_float4(0.f, 0.f, 0.f, 0.f);
            if (gr < Nn) a4 = *(const float4*)&g_h[gr * HIDD + kt * 32 + col];
            *(float4*)&As[row][col] = a4;
        }
        __syncthreads();
#pragma unroll
        for (int k = 0; k < 32; k++) {
            float4 b = *(float4*)&Ws[k][tx * 4];
#pragma unroll
            for (int r = 0; r < 8; r++) {
                float a = As[ty * 8 + r][k];
                acc[r][0] += a * b.x;
                acc[r][1] += a * b.y;
                acc[r][2] += a * b.z;
                acc[r][3] += a * b.w;
            }
        }
        __syncthreads();
    }
#pragma unroll
    for (int r = 0; r < 8; r++) {
        int gr = br + ty * 8 + r;
        if (gr < Nn) {
            float4 o = make_float4(acc[r][0], acc[r][1], acc[r][2], acc[r][3]);
            *(float4*)&g_xs[gr * HIDD + tx * 4] = o;
        }
    }
}

// ---------------- attention logits a_s, a_d (warp per node) ----------------
__global__ void k_att(const float* __restrict__ att_src, const float* __restrict__ att_dst,
                      int l) {
    int gt = blockIdx.x * blockDim.x + threadIdx.x;
    int n = gt >> 5, lane = threadIdx.x & 31;
    if (n >= Nn) return;
    float4 v = *(const float4*)&g_xs[n * HIDD + lane * 4];
    int h = lane >> 3;
    int off = l * HEADS * CH + h * CH + (lane & 7) * 4;
    float4 s = *(const float4*)&att_src[off];
    float4 d = *(const float4*)&att_dst[off];
    float ps = v.x * s.x + v.y * s.y + v.z * s.z + v.w * s.w;
    float pd = v.x * d.x + v.y * d.y + v.z * d.z + v.w * d.w;
    for (int o = 4; o; o >>= 1) {
        ps += __shfl_down_sync(0xffffffffu, ps, o, 8);
        pd += __shfl_down_sync(0xffffffffu, pd, o, 8);
    }
    if ((lane & 7) == 0) {
        g_as[n * HEADS + h] = ps;
        g_ad[n * HEADS + h] = pd;
    }
}

// ---------------- fused edge kernel: warp per dst node ---------------------
// pass1: alpha per edge (lanes parallel), warp-max per head
// pass2: accumulate sum(p*xs[src]) and sum(p); normalize; bias+BN+ReLU+res
__global__ void __launch_bounds__(256) k_edge(const float* __restrict__ conv_b,
                       const float* __restrict__ gamma, const float* __restrict__ beta,
                       const float* __restrict__ mean, const float* __restrict__ var,
                       int l) {
    int warp = (blockIdx.x * blockDim.x + threadIdx.x) >> 5;
    int lane = threadIdx.x & 31;
    if (warp >= Nn) return;
    const int d = warp;
    const int r0 = g_row[d], r1 = g_row[d + 1];
    const float4 ad4 = *(const float4*)&g_ad[d * 4];
    const float4 u4 = *(const float4*)&g_uv[l * 4];
    const float4 v4 = *(const float4*)&g_uv[LL * HEADS + l * 4];

    float mx0 = -1e30f, mx1 = -1e30f, mx2 = -1e30f, mx3 = -1e30f;
    for (int e = r0 + lane; e < r1; e += 32) {
        int s = g_srcs[e];
        float a = g_eas[e];
        float4 as4 = *(const float4*)&g_as[s * 4];
        float a0 = as4.x + ad4.x + a * u4.x + v4.x;
        float a1 = as4.y + ad4.y + a * u4.y + v4.y;
        float a2 = as4.z + ad4.z + a * u4.z + v4.z;
        float a3 = as4.w + ad4.w + a * u4.w + v4.w;
        a0 = (a0 > 0.f) ? a0 : 0.2f * a0;
        a1 = (a1 > 0.f) ? a1 : 0.2f * a1;
        a2 = (a2 > 0.f) ? a2 : 0.2f * a2;
        a3 = (a3 > 0.f) ? a3 : 0.2f * a3;
        mx0 = fmaxf(mx0, a0); mx1 = fmaxf(mx1, a1);
        mx2 = fmaxf(mx2, a2); mx3 = fmaxf(mx3, a3);
        *(float4*)&g_p[e * 4] = make_float4(a0, a1, a2, a3);
    }
#pragma unroll
    for (int o = 16; o; o >>= 1) {
        mx0 = fmaxf(mx0, __shfl_xor_sync(0xffffffffu, mx0, o));
        mx1 = fmaxf(mx1, __shfl_xor_sync(0xffffffffu, mx1, o));
        mx2 = fmaxf(mx2, __shfl_xor_sync(0xffffffffu, mx2, o));
        mx3 = fmaxf(mx3, __shfl_xor_sync(0xffffffffu, mx3, o));
    }
    __syncwarp();

    const int h = lane >> 3;
    const float mxh = (h == 0) ? mx0 : (h == 1) ? mx1 : (h == 2) ? mx2 : mx3;
    float acc0 = 0.f, acc1 = 0.f, acc2 = 0.f, acc3 = 0.f, den = 0.f;
    int e = r0;
    for (; e + 1 < r1; e += 2) {
        int s0 = g_srcs[e], s1 = g_srcs[e + 1];
        float4 q0 = *(const float4*)&g_p[e * 4];
        float4 q1 = *(const float4*)&g_p[(e + 1) * 4];
        float4 x0 = *(const float4*)&g_xs[s0 * HIDD + lane * 4];
        float4 x1 = *(const float4*)&g_xs[s1 * HIDD + lane * 4];
        float al0 = (h == 0) ? q0.x : (h == 1) ? q0.y : (h == 2) ? q0.z : q0.w;
        float al1 = (h == 0) ? q1.x : (h == 1) ? q1.y : (h == 2) ? q1.z : q1.w;
        float p0 = __expf(al0 - mxh);
        float p1 = __expf(al1 - mxh);
        den += p0 + p1;
        acc0 += p0 * x0.x + p1 * x1.x;
        acc1 += p0 * x0.y + p1 * x1.y;
        acc2 += p0 * x0.z + p1 * x1.z;
        acc3 += p0 * x0.w + p1 * x1.w;
    }
    if (e < r1) {
        int s0 = g_srcs[e];
        float4 q0 = *(const float4*)&g_p[e * 4];
        float4 x0 = *(const float4*)&g_xs[s0 * HIDD + lane * 4];
        float al0 = (h == 0) ? q0.x : (h == 1) ? q0.y : (h == 2) ? q0.z : q0.w;
        float p0 = __expf(al0 - mxh);
        den += p0;
        acc0 += p0 * x0.x; acc1 += p0 * x0.y;
        acc2 += p0 * x0.z; acc3 += p0 * x0.w;
    }
    float scale = 1.f / (den + 1e-16f);

    int cb = l * HIDD + lane * 4;
    float4 cb4 = *(const float4*)&conv_b[cb];
    float4 gm4 = *(const float4*)&gamma[cb];
    float4 bt4 = *(const float4*)&beta[cb];
    float4 mn4 = *(const float4*)&mean[cb];
    float4 vr4 = *(const float4*)&var[cb];
    float4 hv = *(const float4*)&g_h[d * HIDD + lane * 4];
    float o0 = (acc0 * scale + cb4.x - mn4.x) * rsqrtf(vr4.x + 1e-5f) * gm4.x + bt4.x;
    float o1 = (acc1 * scale + cb4.y - mn4.y) * rsqrtf(vr4.y + 1e-5f) * gm4.y + bt4.y;
    float o2 = (acc2 * scale + cb4.z - mn4.z) * rsqrtf(vr4.z + 1e-5f) * gm4.z + bt4.z;
    float o3 = (acc3 * scale + cb4.w - mn4.w) * rsqrtf(vr4.w + 1e-5f) * gm4.w + bt4.w;
    hv.x += fmaxf(o0, 0.f);
    hv.y += fmaxf(o1, 0.f);
    hv.z += fmaxf(o2, 0.f);
    hv.w += fmaxf(o3, 0.f);
    *(float4*)&g_h[d * HIDD + lane * 4] = hv;
}

// ---------------- pooling ---------------------------------------------------
__global__ void k_zeropool() {
    int i = blockIdx.x * blockDim.x + threadIdx.x;
    if (i < GG * HIDD) g_pooled[i] = 0.f;
    if (i < GG) g_cnt[i] = 0.f;
}

#define NPB 256
__global__ void k_pool(const int* __restrict__ batch) {
    int c = threadIdx.x;              // 128 channels
    int n0 = blockIdx.x * NPB;
    int n1 = min(n0 + NPB, Nn);
    int cur = -1; float s = 0.f; float cn = 0.f;
    for (int n = n0; n < n1; n++) {
        int g = batch[n];
        if (g != cur) {
            if (cur >= 0) {
                atomicAdd(&g_pooled[cur * HIDD + c], s);
                if (c == 0) atomicAdd(&g_cnt[cur], cn);
            }
            cur = g; s = 0.f; cn = 0.f;
        }
        s += g_h[n * HIDD + c];
        cn += 1.f;
    }
    if (cur >= 0) {
        atomicAdd(&g_pooled[cur * HIDD + c], s);
        if (c == 0) atomicAdd(&g_cnt[cur], cn);
    }
}

// ---------------- classifier head ------------------------------------------
__global__ void k_mlp1(const float* __restrict__ w1, const float* __restrict__ b1) {
    int i = blockIdx.x * blockDim.x + threadIdx.x;   // GG*64
    if (i >= GG * 64) return;
    int g = i >> 6, j = i & 63;
    float cnt = fmaxf(g_cnt[g], 1.f);
    float s = 0.f;
    for (int k = 0; k < HIDD; k++) s += g_pooled[g * HIDD + k] * w1[k * 64 + j];
    g_z[i] = fmaxf(s / cnt + b1[j], 0.f);
}

__global__ void k_mlp2(const float* __restrict__ w2, const float* __restrict__ b2,
                       float* __restrict__ out) {
    int g = threadIdx.x;
    if (g >= GG) return;
    float s = b2[0];
    for (int j = 0; j < 64; j++) s += g_z[g * 64 + j] * w2[j];
    out[g] = 1.f / (1.f + __expf(-s));
}

// ---------------- launch ----------------------------------------------------
extern "C" void kernel_launch(void* const* d_in, const int* in_sizes, int n_in,
                              void* d_out, int out_size) {
    const float* x        = (const float*)d_in[0];
    const float* ea       = (const float*)d_in[1];
    const int*   ei       = (const int*)  d_in[2];
    const int*   batch    = (const int*)  d_in[3];
    const float* enc_w    = (const float*)d_in[4];
    const float* enc_b    = (const float*)d_in[5];
    const float* eenc_w   = (const float*)d_in[6];
    const float* eenc_b   = (const float*)d_in[7];
    const float* lin_w    = (const float*)d_in[8];
    const float* att_src  = (const float*)d_in[9];
    const float* att_dst  = (const float*)d_in[10];
    const float* att_edge = (const float*)d_in[11];
    const float* lin_ew   = (const float*)d_in[12];
    const float* conv_b   = (const float*)d_in[13];
    const float* bn_gamma = (const float*)d_in[14];
    const float* bn_beta  = (const float*)d_in[15];
    const float* bn_mean  = (const float*)d_in[16];
    const float* bn_var   = (const float*)d_in[17];
    const float* w1       = (const float*)d_in[18];
    const float* b1       = (const float*)d_in[19];
    const float* w2       = (const float*)d_in[20];
    const float* b2       = (const float*)d_in[21];
    float* out = (float*)d_out;

    const int TB = 256;
    int gridNH = (Nn * HIDD + TB - 1) / TB;
    int gridE  = (Ee + TB - 1) / TB;
    int gridN  = (Nn + TB - 1) / TB;
    int gridNW = (Nn * 32 + TB - 1) / TB;

    k_enc<<<gridNH, TB>>>(x, enc_w, enc_b);
    k_uv<<<1, 256>>>(eenc_w, eenc_b, lin_ew, att_edge);

    // CSR build (by dst)
    k_hist<<<gridE, TB>>>(ei);
    k_scan1<<<NCHUNK, 256>>>();
    k_scan2<<<1, 32>>>();
    k_scan3<<<gridN, TB>>>();
    k_scatter<<<gridE, TB>>>(ei, ea);

    for (int l = 0; l < LL; l++) {
        k_gemm<<<(Nn + 63) / 64, 256>>>(lin_w + l * HIDD * HIDD);
        k_att<<<gridNW, TB>>>(att_src, att_dst, l);
        k_edge<<<gridNW, TB>>>(conv_b, bn_gamma, bn_beta, bn_mean, bn_var, l);
    }

    k_zeropool<<<(GG * HIDD + TB - 1) / TB, TB>>>();
    k_pool<<<(Nn + NPB - 1) / NPB, 128>>>(batch);
    k_mlp1<<<(GG * 64 + TB - 1) / TB, TB>>>(w1, b1);
    k_mlp2<<<1, 64>>>(w2, b2, out);
}